// round 13
// baseline (speedup 1.0000x reference)
#include <cuda_runtime.h>
#include <cuda_bf16.h>
#include <cstdint>

// Problem constants (fixed by the dataset):
//   x: [B=4096, D=2048], weight: [C=32768, D=2048], weight2: [D, D]
//   out: [B, C] float32
#define DDIM 2048
#define BMAX 4096
#define CMAX 32768
#define EPS_NRM 1e-12f

// Scratch (allocation-free rule: __device__ globals). Every element is
// overwritten on every launch -> deterministic across graph replays.
__device__ float g_inv_cn[DDIM];   // 1 / max(||weight2[:,j]||, eps)
__device__ float g_s[DDIM];        // s[d] = sum_j weight2[d,j] * inv_cn[j]
__device__ float g_xs[BMAX];       // xn . s
__device__ float g_ms[CMAX];       // mean . s

// ---------------------------------------------------------------------------
// Reductions
// ---------------------------------------------------------------------------
__device__ __forceinline__ float2 block_reduce2(float a, float b) {
    #pragma unroll
    for (int o = 16; o; o >>= 1) {
        a += __shfl_xor_sync(0xffffffffu, a, o);
        b += __shfl_xor_sync(0xffffffffu, b, o);
    }
    __shared__ float sa[32], sb[32];
    int w = threadIdx.x >> 5, l = threadIdx.x & 31;
    if (l == 0) { sa[w] = a; sb[w] = b; }
    __syncthreads();
    int nw = (blockDim.x + 31) >> 5;
    a = (threadIdx.x < (unsigned)nw) ? sa[threadIdx.x] : 0.0f;
    b = (threadIdx.x < (unsigned)nw) ? sb[threadIdx.x] : 0.0f;
    if (w == 0) {
        #pragma unroll
        for (int o = 16; o; o >>= 1) {
            a += __shfl_xor_sync(0xffffffffu, a, o);
            b += __shfl_xor_sync(0xffffffffu, b, o);
        }
    }
    return make_float2(a, b);  // valid in thread 0
}

__device__ __forceinline__ float block_reduce1(float a) {
    #pragma unroll
    for (int o = 16; o; o >>= 1) a += __shfl_xor_sync(0xffffffffu, a, o);
    __shared__ float sa[32];
    int w = threadIdx.x >> 5, l = threadIdx.x & 31;
    if (l == 0) sa[w] = a;
    __syncthreads();
    int nw = (blockDim.x + 31) >> 5;
    a = (threadIdx.x < (unsigned)nw) ? sa[threadIdx.x] : 0.0f;
    if (w == 0) {
        #pragma unroll
        for (int o = 16; o; o >>= 1) a += __shfl_xor_sync(0xffffffffu, a, o);
    }
    return a;  // valid in thread 0
}

// ---------------------------------------------------------------------------
// 1) inv column norms of weight2: coalesced tile reduction down the rows.
//    block = (32, 8); warp reads 32 consecutive columns of one row (128B line).
// ---------------------------------------------------------------------------
__global__ void k_colnorm(const float* __restrict__ w2) {
    int j = blockIdx.x * 32 + threadIdx.x;
    float acc = 0.0f;
    #pragma unroll 4
    for (int d = threadIdx.y; d < DDIM; d += 8) {
        float v = __ldg(&w2[(size_t)d * DDIM + j]);
        acc = fmaf(v, v, acc);
    }
    __shared__ float sh[8][32];
    sh[threadIdx.y][threadIdx.x] = acc;
    __syncthreads();
    if (threadIdx.y == 0) {
        float t = 0.0f;
        #pragma unroll
        for (int y = 0; y < 8; y++) t += sh[y][threadIdx.x];
        g_inv_cn[j] = 1.0f / fmaxf(sqrtf(t), EPS_NRM);
    }
}

// ---------------------------------------------------------------------------
// 2) s[d] = sum_j weight2[d,j] * inv_cn[j].  One block per row, float4 loads.
// ---------------------------------------------------------------------------
__global__ void k_rowsum_s(const float* __restrict__ w2) {
    int d = blockIdx.x;
    const float4* row = reinterpret_cast<const float4*>(w2 + (size_t)d * DDIM);
    const float4* icn = reinterpret_cast<const float4*>(g_inv_cn);
    float acc = 0.0f;
    #pragma unroll
    for (int j = threadIdx.x; j < DDIM / 4; j += 256) {
        float4 v = __ldg(&row[j]);
        float4 c = icn[j];
        acc += v.x * c.x + v.y * c.y + v.z * c.z + v.w * c.w;
    }
    float t = block_reduce1(acc);
    if (threadIdx.x == 0) g_s[d] = t;
}

// ---------------------------------------------------------------------------
// 3/4) out[r] = (row . s) / max(||row||, eps).  One block per row.
//      Single pass: dot and sum-of-squares fused -> one read of the matrix.
// ---------------------------------------------------------------------------
__global__ void k_norm_dot(const float* __restrict__ mat, float* __restrict__ out) {
    int r = blockIdx.x;
    const float4* row = reinterpret_cast<const float4*>(mat + (size_t)r * DDIM);
    const float4* sv  = reinterpret_cast<const float4*>(g_s);
    float dot = 0.0f, ss = 0.0f;
    #pragma unroll
    for (int j = threadIdx.x; j < DDIM / 4; j += 256) {
        float4 v  = __ldg(&row[j]);
        float4 s4 = sv[j];
        dot += v.x * s4.x + v.y * s4.y + v.z * s4.z + v.w * s4.w;
        ss  += v.x * v.x  + v.y * v.y  + v.z * v.z  + v.w * v.w;
    }
    float2 t = block_reduce2(dot, ss);
    if (threadIdx.x == 0)
        out[r] = t.x / fmaxf(sqrtf(t.y), EPS_NRM);
}

// ---------------------------------------------------------------------------
// 5) out[b,c] = ms[c] - xs[b].  Pure streaming write (512 MB), float4 STG.
//    grid = (C/(4*256*8), B); each thread writes 8 float4 in one row.
// ---------------------------------------------------------------------------
__global__ void k_logit(float* __restrict__ out, int Cdim) {
    int b = blockIdx.y;
    float xsb = g_xs[b];
    const float4* ms4 = reinterpret_cast<const float4*>(g_ms);
    float4* o4 = reinterpret_cast<float4*>(out) + (size_t)b * (Cdim >> 2);
    int base = blockIdx.x * (256 * 8) + threadIdx.x;
    #pragma unroll
    for (int k = 0; k < 8; k++) {
        int c4 = base + k * 256;
        float4 m = ms4[c4];
        o4[c4] = make_float4(m.x - xsb, m.y - xsb, m.z - xsb, m.w - xsb);
    }
}

// ---------------------------------------------------------------------------
extern "C" void kernel_launch(void* const* d_in, const int* in_sizes, int n_in,
                              void* d_out, int out_size) {
    const float* x  = (const float*)d_in[0];   // [B, D]
    const float* w  = (const float*)d_in[1];   // [C, D]
    const float* w2 = (const float*)d_in[2];   // [D, D]
    float* out = (float*)d_out;                // [B, C]

    const int B = in_sizes[0] / DDIM;          // 4096
    const int C = in_sizes[1] / DDIM;          // 32768

    float* p_xs; cudaGetSymbolAddress((void**)&p_xs, g_xs);
    float* p_ms; cudaGetSymbolAddress((void**)&p_ms, g_ms);

    // 1) inv column norms of weight2
    k_colnorm<<<DDIM / 32, dim3(32, 8)>>>(w2);
    // 2) s = row-sums of scaled weight2
    k_rowsum_s<<<DDIM, 256>>>(w2);
    // 3) xs[b]
    k_norm_dot<<<B, 256>>>(x, p_xs);
    // 4) ms[c]  (256 MB read — the big one besides the output)
    k_norm_dot<<<C, 256>>>(w, p_ms);
    // 5) logit stream-out (512 MB write)
    dim3 grid5(C / (4 * 256 * 8), B);
    k_logit<<<grid5, 256>>>(out, C);
}

// round 14
// speedup vs baseline: 1.2456x; 1.2456x over previous
#include <cuda_runtime.h>
#include <cuda_bf16.h>
#include <cstdint>

// Problem constants (fixed by the dataset):
//   x: [B=4096, D=2048], weight: [C=32768, D=2048], weight2: [D, D]
//   out: [B, C] float32
#define DDIM 2048
#define BMAX 4096
#define CMAX 32768
#define EPS_NRM 1e-12f

// Scratch (allocation-free rule: __device__ globals). Every element is
// overwritten on every launch -> deterministic across graph replays.
__device__ float g_inv_cn[DDIM];   // 1 / max(||weight2[:,j]||, eps)
__device__ float g_s[DDIM];        // s[d] = sum_j weight2[d,j] * inv_cn[j]
__device__ float g_xs[BMAX];       // xn . s
__device__ float g_ms[CMAX];       // mean . s

__device__ __forceinline__ float block_reduce1(float a) {
    #pragma unroll
    for (int o = 16; o; o >>= 1) a += __shfl_xor_sync(0xffffffffu, a, o);
    __shared__ float sa[32];
    int w = threadIdx.x >> 5, l = threadIdx.x & 31;
    if (l == 0) sa[w] = a;
    __syncthreads();
    int nw = (blockDim.x + 31) >> 5;
    a = (threadIdx.x < (unsigned)nw) ? sa[threadIdx.x] : 0.0f;
    if (w == 0) {
        #pragma unroll
        for (int o = 16; o; o >>= 1) a += __shfl_xor_sync(0xffffffffu, a, o);
    }
    return a;  // valid in thread 0
}

// ---------------------------------------------------------------------------
// 1) inv column norms of weight2. block = (32, 16) = 512 threads; warp reads a
//    full 128B row segment. Only 64 blocks exist (=64 SMs), so go wide per SM.
// ---------------------------------------------------------------------------
__global__ void k_colnorm(const float* __restrict__ w2) {
    int j = blockIdx.x * 32 + threadIdx.x;
    float acc = 0.0f;
    #pragma unroll 8
    for (int d = threadIdx.y; d < DDIM; d += 16) {
        float v = __ldcs(&w2[(size_t)d * DDIM + j]);
        acc = fmaf(v, v, acc);
    }
    __shared__ float sh[16][32];
    sh[threadIdx.y][threadIdx.x] = acc;
    __syncthreads();
    if (threadIdx.y == 0) {
        float t = 0.0f;
        #pragma unroll
        for (int y = 0; y < 16; y++) t += sh[y][threadIdx.x];
        g_inv_cn[j] = 1.0f / fmaxf(sqrtf(t), EPS_NRM);
    }
}

// ---------------------------------------------------------------------------
// 2) s[d] = sum_j weight2[d,j] * inv_cn[j]. One block per row; w2 is L2-hot
//    (16 MB, just read by k_colnorm), so this is cheap.
// ---------------------------------------------------------------------------
__global__ void k_rowsum_s(const float* __restrict__ w2) {
    int d = blockIdx.x;
    const float4* row = reinterpret_cast<const float4*>(w2 + (size_t)d * DDIM);
    const float4* icn = reinterpret_cast<const float4*>(g_inv_cn);
    float acc = 0.0f;
    #pragma unroll
    for (int j = threadIdx.x; j < DDIM / 4; j += 256) {
        float4 v = __ldg(&row[j]);
        float4 c = icn[j];
        acc += v.x * c.x + v.y * c.y + v.z * c.z + v.w * c.w;
    }
    float t = block_reduce1(acc);
    if (threadIdx.x == 0) g_s[d] = t;
}

// ---------------------------------------------------------------------------
// 3) Fused xs/ms: one WARP per row. 16 float4 per lane in bursts of 8
//    outstanding LDG.128 (streamed, __ldcs), s staged in SMEM once per block,
//    shuffle-only reduction -> no __syncthreads in the hot path, no tiny-block
//    tail. First B warps do x -> g_xs, the rest do weight -> g_ms.
// ---------------------------------------------------------------------------
__global__ void k_norm_dot_fused(const float* __restrict__ xmat,
                                 const float* __restrict__ wmat,
                                 int B) {
    __shared__ float4 s_sh[DDIM / 4];   // 8 KB
    {
        const float4* sv = reinterpret_cast<const float4*>(g_s);
        #pragma unroll
        for (int i = threadIdx.x; i < DDIM / 4; i += 256) s_sh[i] = sv[i];
    }
    __syncthreads();

    int warp = threadIdx.x >> 5;
    int lane = threadIdx.x & 31;
    int gr = blockIdx.x * 8 + warp;      // global row id over B + C rows

    const float* mat;
    float* outp;
    int r;
    if (gr < B) { mat = xmat; outp = g_xs; r = gr; }
    else        { mat = wmat; outp = g_ms; r = gr - B; }

    const float4* row = reinterpret_cast<const float4*>(mat + (size_t)r * DDIM);
    float dot = 0.0f, ss = 0.0f;

    #pragma unroll
    for (int i = 0; i < 4; i++) {
        float4 a[4];
        #pragma unroll
        for (int k = 0; k < 4; k++)
            a[k] = __ldcs(&row[lane + (i * 4 + k) * 32]);
        #pragma unroll
        for (int k = 0; k < 4; k++) {
            float4 s4 = s_sh[lane + (i * 4 + k) * 32];
            dot += a[k].x * s4.x + a[k].y * s4.y + a[k].z * s4.z + a[k].w * s4.w;
            ss  += a[k].x * a[k].x + a[k].y * a[k].y + a[k].z * a[k].z + a[k].w * a[k].w;
        }
    }

    #pragma unroll
    for (int o = 16; o; o >>= 1) {
        dot += __shfl_xor_sync(0xffffffffu, dot, o);
        ss  += __shfl_xor_sync(0xffffffffu, ss, o);
    }
    if (lane == 0)
        outp[r] = dot / fmaxf(sqrtf(ss), EPS_NRM);
}

// ---------------------------------------------------------------------------
// 4) out[b,c] = ms[c] - xs[b]. 512 MB streaming write. Batch all 8 ms loads
//    (L2-resident, 128 KB) before the 8 stores; __stcs so the output stream
//    doesn't churn L2.
// ---------------------------------------------------------------------------
__global__ void k_logit(float* __restrict__ out, int Cdim) {
    int b = blockIdx.y;
    float xsb = g_xs[b];
    const float4* ms4 = reinterpret_cast<const float4*>(g_ms);
    float4* o4 = reinterpret_cast<float4*>(out) + (size_t)b * (Cdim >> 2);
    int base = blockIdx.x * (256 * 8) + threadIdx.x;

    float4 m[8];
    #pragma unroll
    for (int k = 0; k < 8; k++)
        m[k] = __ldg(&ms4[base + k * 256]);
    #pragma unroll
    for (int k = 0; k < 8; k++) {
        float4 r = make_float4(m[k].x - xsb, m[k].y - xsb,
                               m[k].z - xsb, m[k].w - xsb);
        __stcs(&o4[base + k * 256], r);
    }
}

// ---------------------------------------------------------------------------
extern "C" void kernel_launch(void* const* d_in, const int* in_sizes, int n_in,
                              void* d_out, int out_size) {
    const float* x  = (const float*)d_in[0];   // [B, D]
    const float* w  = (const float*)d_in[1];   // [C, D]
    const float* w2 = (const float*)d_in[2];   // [D, D]
    float* out = (float*)d_out;                // [B, C]

    const int B = in_sizes[0] / DDIM;          // 4096
    const int C = in_sizes[1] / DDIM;          // 32768

    // 1) inv column norms of weight2
    k_colnorm<<<DDIM / 32, dim3(32, 16)>>>(w2);
    // 2) s = row-sums of scaled weight2 (L2-hot)
    k_rowsum_s<<<DDIM, 256>>>(w2);
    // 3) xs[b] and ms[c] fused, warp-per-row
    k_norm_dot_fused<<<(B + C) / 8, 256>>>(x, w, B);
    // 4) logit stream-out (512 MB write)
    dim3 grid4(C / (4 * 256 * 8), B);
    k_logit<<<grid4, 256>>>(out, C);
}

// round 15
// speedup vs baseline: 1.2543x; 1.0070x over previous
#include <cuda_runtime.h>
#include <cuda_bf16.h>
#include <cstdint>

// Problem constants (fixed by the dataset):
//   x: [B=4096, D=2048], weight: [C=32768, D=2048], weight2: [D, D]
//   out: [B, C] float32
#define DDIM 2048
#define BMAX 4096
#define CMAX 32768
#define EPS_NRM 1e-12f

// Scratch (allocation-free rule: __device__ globals). Every element is
// overwritten on every launch -> deterministic across graph replays.
__device__ float g_part[4][DDIM];  // partial column sum-of-squares of weight2
__device__ float g_inv_cn[DDIM];   // 1 / max(||weight2[:,j]||, eps)
__device__ float g_s[DDIM];        // s[d] = sum_j weight2[d,j] * inv_cn[j]
__device__ float g_xs[BMAX];       // xn . s
__device__ float g_ms[CMAX];       // mean . s

__device__ __forceinline__ float block_reduce1(float a) {
    #pragma unroll
    for (int o = 16; o; o >>= 1) a += __shfl_xor_sync(0xffffffffu, a, o);
    __shared__ float sa[32];
    int w = threadIdx.x >> 5, l = threadIdx.x & 31;
    if (l == 0) sa[w] = a;
    __syncthreads();
    int nw = (blockDim.x + 31) >> 5;
    a = (threadIdx.x < (unsigned)nw) ? sa[threadIdx.x] : 0.0f;
    if (w == 0) {
        #pragma unroll
        for (int o = 16; o; o >>= 1) a += __shfl_xor_sync(0xffffffffu, a, o);
    }
    return a;  // valid in thread 0
}

// ---------------------------------------------------------------------------
// 1a) Partial column sum-of-squares of weight2. grid (64, 4): blockIdx.y picks
//     a 512-row chunk of d -> 256 blocks so all 148 SMs pull on the 16 MB read.
// ---------------------------------------------------------------------------
__global__ void k_colnorm_part(const float* __restrict__ w2) {
    int j = blockIdx.x * 32 + threadIdx.x;
    int d0 = blockIdx.y * (DDIM / 4);
    float acc = 0.0f;
    #pragma unroll 8
    for (int d = threadIdx.y; d < DDIM / 4; d += 16) {
        float v = __ldcs(&w2[(size_t)(d0 + d) * DDIM + j]);
        acc = fmaf(v, v, acc);
    }
    __shared__ float sh[16][32];
    sh[threadIdx.y][threadIdx.x] = acc;
    __syncthreads();
    if (threadIdx.y == 0) {
        float t = 0.0f;
        #pragma unroll
        for (int y = 0; y < 16; y++) t += sh[y][threadIdx.x];
        g_part[blockIdx.y][j] = t;
    }
}

// 1b) inv_cn[j] = 1 / max(sqrt(sum of 4 partials), eps)
__global__ void k_colnorm_fin() {
    int j = blockIdx.x * 256 + threadIdx.x;
    float t = g_part[0][j] + g_part[1][j] + g_part[2][j] + g_part[3][j];
    g_inv_cn[j] = 1.0f / fmaxf(sqrtf(t), EPS_NRM);
}

// ---------------------------------------------------------------------------
// 2) s[d] = sum_j weight2[d,j] * inv_cn[j]. One block per row; w2 is L2-hot
//    (16 MB, just read by k_colnorm), so this is cheap.
// ---------------------------------------------------------------------------
__global__ void k_rowsum_s(const float* __restrict__ w2) {
    int d = blockIdx.x;
    const float4* row = reinterpret_cast<const float4*>(w2 + (size_t)d * DDIM);
    const float4* icn = reinterpret_cast<const float4*>(g_inv_cn);
    float acc = 0.0f;
    #pragma unroll
    for (int j = threadIdx.x; j < DDIM / 4; j += 256) {
        float4 v = __ldg(&row[j]);
        float4 c = icn[j];
        acc += v.x * c.x + v.y * c.y + v.z * c.z + v.w * c.w;
    }
    float t = block_reduce1(acc);
    if (threadIdx.x == 0) g_s[d] = t;
}

// ---------------------------------------------------------------------------
// 3) Fused xs/ms: one WARP per row, bursts of 8 outstanding LDG.128 per lane,
//    s staged once per block in SMEM, shuffle-only reduction.
//    First B warps do x -> g_xs, the rest do weight -> g_ms.
// ---------------------------------------------------------------------------
__global__ void k_norm_dot_fused(const float* __restrict__ xmat,
                                 const float* __restrict__ wmat,
                                 int B) {
    __shared__ float4 s_sh[DDIM / 4];   // 8 KB
    {
        const float4* sv = reinterpret_cast<const float4*>(g_s);
        #pragma unroll
        for (int i = threadIdx.x; i < DDIM / 4; i += 256) s_sh[i] = sv[i];
    }
    __syncthreads();

    int warp = threadIdx.x >> 5;
    int lane = threadIdx.x & 31;
    int gr = blockIdx.x * 8 + warp;      // global row id over B + C rows

    const float* mat;
    float* outp;
    int r;
    if (gr < B) { mat = xmat; outp = g_xs; r = gr; }
    else        { mat = wmat; outp = g_ms; r = gr - B; }

    const float4* row = reinterpret_cast<const float4*>(mat + (size_t)r * DDIM);
    float dot = 0.0f, ss = 0.0f;

    #pragma unroll
    for (int i = 0; i < 2; i++) {
        float4 a[8];
        #pragma unroll
        for (int k = 0; k < 8; k++)
            a[k] = __ldcs(&row[lane + (i * 8 + k) * 32]);
        #pragma unroll
        for (int k = 0; k < 8; k++) {
            float4 s4 = s_sh[lane + (i * 8 + k) * 32];
            dot += a[k].x * s4.x + a[k].y * s4.y + a[k].z * s4.z + a[k].w * s4.w;
            ss  += a[k].x * a[k].x + a[k].y * a[k].y + a[k].z * a[k].z + a[k].w * a[k].w;
        }
    }

    #pragma unroll
    for (int o = 16; o; o >>= 1) {
        dot += __shfl_xor_sync(0xffffffffu, dot, o);
        ss  += __shfl_xor_sync(0xffffffffu, ss, o);
    }
    if (lane == 0)
        outp[r] = dot / fmaxf(sqrtf(ss), EPS_NRM);
}

// ---------------------------------------------------------------------------
// 4) out[b,c] = ms[c] - xs[b]. b-tiled: each block owns a [16 b x 2048 c]
//    tile, reads its ms chunk ONCE into registers (2 float4/thread), stages
//    16 xs in SMEM, streams 32 float4 stores (__stcs -> no L2 churn).
//    Cuts ms L2 read traffic 128 MB -> 32 MB so the LTS cap goes to writes.
// ---------------------------------------------------------------------------
#define TILE_B 16
__global__ void k_logit(float* __restrict__ out, int Cdim) {
    __shared__ float s_xs[TILE_B];
    if (threadIdx.x < TILE_B)
        s_xs[threadIdx.x] = g_xs[blockIdx.y * TILE_B + threadIdx.x];
    __syncthreads();

    const float4* ms4 = reinterpret_cast<const float4*>(g_ms);
    int c4_0 = blockIdx.x * 512 + threadIdx.x;        // 2048 c = 512 float4
    int c4_1 = c4_0 + 256;
    float4 m0 = __ldg(&ms4[c4_0]);
    float4 m1 = __ldg(&ms4[c4_1]);

    size_t rowq = (size_t)(Cdim >> 2);
    float4* o4 = reinterpret_cast<float4*>(out) +
                 (size_t)blockIdx.y * TILE_B * rowq;

    #pragma unroll
    for (int bb = 0; bb < TILE_B; bb++) {
        float xsb = s_xs[bb];
        float4 r0 = make_float4(m0.x - xsb, m0.y - xsb, m0.z - xsb, m0.w - xsb);
        float4 r1 = make_float4(m1.x - xsb, m1.y - xsb, m1.z - xsb, m1.w - xsb);
        __stcs(&o4[bb * rowq + c4_0], r0);
        __stcs(&o4[bb * rowq + c4_1], r1);
    }
}

// ---------------------------------------------------------------------------
extern "C" void kernel_launch(void* const* d_in, const int* in_sizes, int n_in,
                              void* d_out, int out_size) {
    const float* x  = (const float*)d_in[0];   // [B, D]
    const float* w  = (const float*)d_in[1];   // [C, D]
    const float* w2 = (const float*)d_in[2];   // [D, D]
    float* out = (float*)d_out;                // [B, C]

    const int B = in_sizes[0] / DDIM;          // 4096
    const int C = in_sizes[1] / DDIM;          // 32768

    // 1) inv column norms of weight2 (partials over 4 d-chunks, then finalize)
    k_colnorm_part<<<dim3(DDIM / 32, 4), dim3(32, 16)>>>(w2);
    k_colnorm_fin<<<DDIM / 256, 256>>>();
    // 2) s = row-sums of scaled weight2 (L2-hot)
    k_rowsum_s<<<DDIM, 256>>>(w2);
    // 3) xs[b] and ms[c] fused, warp-per-row
    k_norm_dot_fused<<<(B + C) / 8, 256>>>(x, w, B);
    // 4) logit stream-out (512 MB write), b-tiled 16x2048
    dim3 grid4(C / 2048, B / TILE_B);
    k_logit<<<grid4, 256>>>(out, C);
}